// round 1
// baseline (speedup 1.0000x reference)
#include <cuda_runtime.h>
#include <math.h>

// Problem constants
#define BATCH 4
#define LSEQ 4096
#define DDIM 256
#define NTOK (BATCH * LSEQ)   // 16384
#define INV_TAU 2.0f          // 1 / 0.5

// GEMM tiling
#define BM 128
#define BN 128
#define BK 16

// ---------------- scratch (device globals; no allocation allowed) -------------
__device__ float g_H [NTOK * DDIM];   // ELU(X@W1^T+b1), reused for both inputs
__device__ float g_Z1[NTOK * DDIM];   // projected+normalized z1
__device__ float g_Z2[NTOK * DDIM];
__device__ float g_R11 [NTOK];        // rowsum exp(z1.z1/tau)
__device__ float g_R22 [NTOK];        // rowsum exp(z2.z2/tau)
__device__ float g_R12r[NTOK];        // rowsum exp(z1.z2/tau)
__device__ float g_R12c[NTOK];        // colsum exp(z1.z2/tau)
__device__ float g_D12 [NTOK];        // exp(diag(z1.z2)/tau)

__device__ __forceinline__ float* selZ(int s) { return s == 1 ? g_Z1 : g_Z2; }
__device__ __forceinline__ float* selR(int s) {
    return s == 0 ? g_R11 : (s == 1 ? g_R22 : g_R12r);
}

// ---------------- init -----------------------------------------------------
__global__ void zero_kernel() {
    int i = blockIdx.x * blockDim.x + threadIdx.x;
    if (i < NTOK) {
        g_R11[i] = 0.f; g_R22[i] = 0.f; g_R12r[i] = 0.f; g_R12c[i] = 0.f;
    }
}

// ---------------- projection GEMM (NT): C = act(A @ W^T + bias) ------------
// A: [16384, 256] (row-major, K contiguous). W: [256, 256] (row-major, K contig).
// ACT: 0 = identity, 1 = ELU.  srcH: if nonzero, read A from g_H instead of param.
// dst: 0 -> g_H, 1 -> g_Z1, 2 -> g_Z2.
template <int ACT>
__global__ __launch_bounds__(256, 2)
void gemm_nt_bias(const float* __restrict__ Ain, const float* __restrict__ W,
                  const float* __restrict__ bias, int srcH, int dst) {
    __shared__ float As[BK][BM];
    __shared__ float Bs[BK][BN];

    const float* A = srcH ? g_H : Ain;
    float* C = (dst == 0) ? g_H : (dst == 1 ? g_Z1 : g_Z2);

    const int bm = blockIdx.y * BM;
    const int bn = blockIdx.x * BN;
    const int tid = threadIdx.x;
    const int tx = tid & 15, ty = tid >> 4;

    float acc[8][8];
#pragma unroll
    for (int i = 0; i < 8; i++)
#pragma unroll
        for (int j = 0; j < 8; j++) acc[i][j] = 0.f;

    for (int k0 = 0; k0 < DDIM; k0 += BK) {
#pragma unroll
        for (int it = 0; it < 2; it++) {
            int idx = tid + it * 256;          // 0..511
            int row = idx >> 2;                // 0..127
            int kc  = (idx & 3) << 2;          // 0,4,8,12
            float4 va = *reinterpret_cast<const float4*>(A + (size_t)(bm + row) * DDIM + k0 + kc);
            As[kc + 0][row] = va.x; As[kc + 1][row] = va.y;
            As[kc + 2][row] = va.z; As[kc + 3][row] = va.w;
            float4 vb = *reinterpret_cast<const float4*>(W + (size_t)(bn + row) * DDIM + k0 + kc);
            Bs[kc + 0][row] = vb.x; Bs[kc + 1][row] = vb.y;
            Bs[kc + 2][row] = vb.z; Bs[kc + 3][row] = vb.w;
        }
        __syncthreads();
#pragma unroll
        for (int k = 0; k < BK; k++) {
            float4 a0 = *reinterpret_cast<const float4*>(&As[k][ty * 8]);
            float4 a1 = *reinterpret_cast<const float4*>(&As[k][ty * 8 + 4]);
            float4 b0 = *reinterpret_cast<const float4*>(&Bs[k][tx * 8]);
            float4 b1 = *reinterpret_cast<const float4*>(&Bs[k][tx * 8 + 4]);
            float a[8] = {a0.x, a0.y, a0.z, a0.w, a1.x, a1.y, a1.z, a1.w};
            float b[8] = {b0.x, b0.y, b0.z, b0.w, b1.x, b1.y, b1.z, b1.w};
#pragma unroll
            for (int i = 0; i < 8; i++)
#pragma unroll
                for (int j = 0; j < 8; j++) acc[i][j] = fmaf(a[i], b[j], acc[i][j]);
        }
        __syncthreads();
    }

    float bv[8];
#pragma unroll
    for (int j = 0; j < 8; j++) bv[j] = bias[bn + tx * 8 + j];
#pragma unroll
    for (int i = 0; i < 8; i++) {
        float* crow = C + (size_t)(bm + ty * 8 + i) * DDIM + bn + tx * 8;
#pragma unroll
        for (int j = 0; j < 8; j++) {
            float v = acc[i][j] + bv[j];
            if (ACT) v = v > 0.f ? v : expm1f(v);
            crow[j] = v;
        }
    }
}

// ---------------- row normalization (in place) ------------------------------
__global__ void normalize_kernel() {
    float* Z = (blockIdx.y == 0) ? g_Z1 : g_Z2;
    int row  = blockIdx.x * 8 + (threadIdx.x >> 5);
    int lane = threadIdx.x & 31;
    float4* p = reinterpret_cast<float4*>(Z + (size_t)row * DDIM);
    float4 v0 = p[lane];
    float4 v1 = p[lane + 32];
    float s = v0.x*v0.x + v0.y*v0.y + v0.z*v0.z + v0.w*v0.w
            + v1.x*v1.x + v1.y*v1.y + v1.z*v1.z + v1.w*v1.w;
#pragma unroll
    for (int off = 16; off >= 1; off >>= 1) s += __shfl_xor_sync(0xffffffffu, s, off);
    float inv = 1.f / fmaxf(sqrtf(s), 1e-12f);
    v0.x *= inv; v0.y *= inv; v0.z *= inv; v0.w *= inv;
    v1.x *= inv; v1.y *= inv; v1.z *= inv; v1.w *= inv;
    p[lane] = v0; p[lane + 32] = v1;
}

// ---------------- diagonal of exp(z1.z2/tau) --------------------------------
__global__ void diag_kernel() {
    int row  = blockIdx.x * 8 + (threadIdx.x >> 5);
    int lane = threadIdx.x & 31;
    const float4* p1 = reinterpret_cast<const float4*>(g_Z1 + (size_t)row * DDIM);
    const float4* p2 = reinterpret_cast<const float4*>(g_Z2 + (size_t)row * DDIM);
    float4 a0 = p1[lane], a1 = p1[lane + 32];
    float4 b0 = p2[lane], b1 = p2[lane + 32];
    float s = a0.x*b0.x + a0.y*b0.y + a0.z*b0.z + a0.w*b0.w
            + a1.x*b1.x + a1.y*b1.y + a1.z*b1.z + a1.w*b1.w;
#pragma unroll
    for (int off = 16; off >= 1; off >>= 1) s += __shfl_xor_sync(0xffffffffu, s, off);
    if (lane == 0) g_D12[row] = __expf(s * INV_TAU);
}

// ---------------- Gram: row/col sums of exp(ZA ZB^T / tau) -----------------
// selA/selB: 1->g_Z1, 2->g_Z2. rsel: 0->R11, 1->R22, 2->R12r. COL: also fill R12c.
template <bool COL>
__global__ __launch_bounds__(256, 2)
void gram_kernel(int selA, int selB, int rsel) {
    __shared__ float As[BK][BM];
    __shared__ float Bs[BK][BN];
    __shared__ float colred[BN];

    const int b = blockIdx.z;
    const float* A = selZ(selA) + (size_t)b * LSEQ * DDIM;
    const float* Bp = selZ(selB) + (size_t)b * LSEQ * DDIM;
    float* rowsum = selR(rsel);

    const int bm = blockIdx.y * BM;
    const int bn = blockIdx.x * BN;
    const int tid = threadIdx.x;
    const int tx = tid & 15, ty = tid >> 4;

    float acc[8][8];
#pragma unroll
    for (int i = 0; i < 8; i++)
#pragma unroll
        for (int j = 0; j < 8; j++) acc[i][j] = 0.f;

    for (int k0 = 0; k0 < DDIM; k0 += BK) {
#pragma unroll
        for (int it = 0; it < 2; it++) {
            int idx = tid + it * 256;
            int row = idx >> 2;
            int kc  = (idx & 3) << 2;
            float4 va = *reinterpret_cast<const float4*>(A + (size_t)(bm + row) * DDIM + k0 + kc);
            As[kc + 0][row] = va.x; As[kc + 1][row] = va.y;
            As[kc + 2][row] = va.z; As[kc + 3][row] = va.w;
            float4 vb = *reinterpret_cast<const float4*>(Bp + (size_t)(bn + row) * DDIM + k0 + kc);
            Bs[kc + 0][row] = vb.x; Bs[kc + 1][row] = vb.y;
            Bs[kc + 2][row] = vb.z; Bs[kc + 3][row] = vb.w;
        }
        __syncthreads();
#pragma unroll
        for (int k = 0; k < BK; k++) {
            float4 a0 = *reinterpret_cast<const float4*>(&As[k][ty * 8]);
            float4 a1 = *reinterpret_cast<const float4*>(&As[k][ty * 8 + 4]);
            float4 b0 = *reinterpret_cast<const float4*>(&Bs[k][tx * 8]);
            float4 b1 = *reinterpret_cast<const float4*>(&Bs[k][tx * 8 + 4]);
            float a[8] = {a0.x, a0.y, a0.z, a0.w, a1.x, a1.y, a1.z, a1.w};
            float bb[8] = {b0.x, b0.y, b0.z, b0.w, b1.x, b1.y, b1.z, b1.w};
#pragma unroll
            for (int i = 0; i < 8; i++)
#pragma unroll
                for (int j = 0; j < 8; j++) acc[i][j] = fmaf(a[i], bb[j], acc[i][j]);
        }
        __syncthreads();
    }

    // epilogue: exp + per-thread row/col partial sums
    float rpart[8], cpart[8];
#pragma unroll
    for (int i = 0; i < 8; i++) rpart[i] = 0.f;
#pragma unroll
    for (int j = 0; j < 8; j++) cpart[j] = 0.f;
#pragma unroll
    for (int i = 0; i < 8; i++)
#pragma unroll
        for (int j = 0; j < 8; j++) {
            float v = __expf(acc[i][j] * INV_TAU);
            rpart[i] += v;
            cpart[j] += v;
        }

    // row reduce across the 16 tx lanes (xor offsets < 16 stay within the group)
#pragma unroll
    for (int off = 8; off >= 1; off >>= 1)
#pragma unroll
        for (int i = 0; i < 8; i++) rpart[i] += __shfl_xor_sync(0xffffffffu, rpart[i], off);
    if (tx == 0) {
#pragma unroll
        for (int i = 0; i < 8; i++)
            atomicAdd(&rowsum[b * LSEQ + bm + ty * 8 + i], rpart[i]);
    }

    if (COL) {
        // combine the two ty's within each warp
#pragma unroll
        for (int j = 0; j < 8; j++) cpart[j] += __shfl_xor_sync(0xffffffffu, cpart[j], 16);
        if (tid < BN) colred[tid] = 0.f;
        __syncthreads();
        if ((tid & 16) == 0) {   // lanes 0..15 of each warp hold the combined sums
#pragma unroll
            for (int j = 0; j < 8; j++) atomicAdd(&colred[tx * 8 + j], cpart[j]);
        }
        __syncthreads();
        if (tid < BN) atomicAdd(&g_R12c[b * LSEQ + bn + tid], colred[tid]);
    }
}

// ---------------- final scalar reduction ------------------------------------
__global__ void final_kernel(float* __restrict__ out) {
    __shared__ double sred[256];
    const float E2 = 7.3890560989306495f;   // exp(||z||^2 / tau) = exp(2)
    double acc = 0.0;
    for (int n = threadIdx.x; n < NTOK; n += 256) {
        float d1 = g_R11[n] + g_R12r[n] - E2;
        float d2 = g_R22[n] + g_R12c[n] - E2;
        acc += (double)(logf(d1) + logf(d2) - 2.f * logf(g_D12[n]));
    }
    sred[threadIdx.x] = acc;
    __syncthreads();
    for (int s = 128; s > 0; s >>= 1) {
        if (threadIdx.x < s) sred[threadIdx.x] += sred[threadIdx.x + s];
        __syncthreads();
    }
    if (threadIdx.x == 0) out[0] = (float)(sred[0] / (2.0 * BATCH));
}

// ---------------- launch -----------------------------------------------------
extern "C" void kernel_launch(void* const* d_in, const int* in_sizes, int n_in,
                              void* d_out, int out_size) {
    (void)in_sizes; (void)n_in; (void)out_size;
    const float* X1 = (const float*)d_in[0];
    const float* X2 = (const float*)d_in[1];
    const float* W1 = (const float*)d_in[2];
    const float* b1 = (const float*)d_in[3];
    const float* W2 = (const float*)d_in[4];
    const float* b2 = (const float*)d_in[5];
    float* out = (float*)d_out;

    zero_kernel<<<(NTOK + 255) / 256, 256>>>();

    dim3 gproj(DDIM / BN, NTOK / BM);     // (2, 128)
    // z1 = proj(X1)
    gemm_nt_bias<1><<<gproj, 256>>>(X1, W1, b1, /*srcH=*/0, /*dst=*/0);
    gemm_nt_bias<0><<<gproj, 256>>>(nullptr, W2, b2, /*srcH=*/1, /*dst=*/1);
    // z2 = proj(X2)
    gemm_nt_bias<1><<<gproj, 256>>>(X2, W1, b1, /*srcH=*/0, /*dst=*/0);
    gemm_nt_bias<0><<<gproj, 256>>>(nullptr, W2, b2, /*srcH=*/1, /*dst=*/2);

    normalize_kernel<<<dim3(NTOK / 8, 2), 256>>>();
    diag_kernel<<<NTOK / 8, 256>>>();

    dim3 ggram(LSEQ / BN, LSEQ / BM, BATCH);   // (32, 32, 4)
    gram_kernel<false><<<ggram, 256>>>(1, 1, 0);   // R11
    gram_kernel<false><<<ggram, 256>>>(2, 2, 1);   // R22
    gram_kernel<true ><<<ggram, 256>>>(1, 2, 2);   // R12 row + col

    final_kernel<<<1, 256>>>(out);
}

// round 3
// speedup vs baseline: 3.9396x; 3.9396x over previous
#include <cuda_runtime.h>
#include <cuda_bf16.h>
#include <math.h>
#include <stdint.h>

// Problem constants
#define BATCH 4
#define LSEQ 4096
#define DDIM 256
#define NTOK (BATCH * LSEQ)   // 16384
#define INV_TAU 2.0f

// Projection GEMM tiling (f32 SIMT)
#define BM 128
#define BN 128
#define BK 16

// Gram tiling (warp MMA): CTA 128x128, K staged 64 at a time, double buffered
#define GBM 128
#define GBN 128
#define GBK 64
#define GPAD 72                      // halves per SMEM row (64 + 8 pad)
#define G_TILE_BYTES (GBM * GPAD * 2)      // 18432 per buffer
#define G_B_OFF (2 * G_TILE_BYTES)         // B tiles start after A double buffer
#define G_SMEM_TOTAL (4 * G_TILE_BYTES)    // 73728

// ---------------- scratch (device globals; no allocation allowed) -----------
__device__ float g_H [NTOK * DDIM];
__device__ float g_Z1[NTOK * DDIM];
__device__ float g_Z2[NTOK * DDIM];
__device__ __nv_bfloat16 g_Z1h[NTOK * DDIM];
__device__ __nv_bfloat16 g_Z2h[NTOK * DDIM];
__device__ float g_R11 [NTOK];
__device__ float g_R22 [NTOK];
__device__ float g_R12r[NTOK];
__device__ float g_R12c[NTOK];
__device__ float g_D12 [NTOK];

// ---------------- PTX helpers ------------------------------------------------
__device__ __forceinline__ uint32_t smem_u32(const void* p) {
    uint32_t a;
    asm("{ .reg .u64 t; cvta.to.shared.u64 t, %1; cvt.u32.u64 %0, t; }"
        : "=r"(a) : "l"(p));
    return a;
}

__device__ __forceinline__ void cp_async16(uint32_t s, const void* g) {
    asm volatile("cp.async.cg.shared.global [%0], [%1], 16;" :: "r"(s), "l"(g));
}
__device__ __forceinline__ void cp_commit() {
    asm volatile("cp.async.commit_group;");
}
template <int N>
__device__ __forceinline__ void cp_wait() {
    asm volatile("cp.async.wait_group %0;" :: "n"(N));
}

__device__ __forceinline__ void ldm_x4(uint32_t& r0, uint32_t& r1, uint32_t& r2,
                                       uint32_t& r3, uint32_t addr) {
    asm volatile("ldmatrix.sync.aligned.m8n8.x4.shared.b16 {%0,%1,%2,%3}, [%4];"
                 : "=r"(r0), "=r"(r1), "=r"(r2), "=r"(r3) : "r"(addr));
}

__device__ __forceinline__ void mma_bf16(float* d, const uint32_t* a,
                                         const uint32_t* b) {
    asm volatile(
        "mma.sync.aligned.m16n8k16.row.col.f32.bf16.bf16.f32 "
        "{%0,%1,%2,%3}, {%4,%5,%6,%7}, {%8,%9}, {%0,%1,%2,%3};"
        : "+f"(d[0]), "+f"(d[1]), "+f"(d[2]), "+f"(d[3])
        : "r"(a[0]), "r"(a[1]), "r"(a[2]), "r"(a[3]), "r"(b[0]), "r"(b[1]));
}

// ---------------- init -------------------------------------------------------
__global__ void zero_kernel() {
    int i = blockIdx.x * blockDim.x + threadIdx.x;
    if (i < NTOK) {
        g_R11[i] = 0.f; g_R22[i] = 0.f; g_R12r[i] = 0.f; g_R12c[i] = 0.f;
    }
}

// ---------------- projection GEMM (NT, f32 SIMT): C = act(A @ W^T + bias) ---
template <int ACT>
__global__ __launch_bounds__(256, 2)
void gemm_nt_bias(const float* __restrict__ Ain, const float* __restrict__ W,
                  const float* __restrict__ bias, int srcH, int dst) {
    __shared__ float As[BK][BM];
    __shared__ float Bs[BK][BN];

    const float* A = srcH ? g_H : Ain;
    float* C = (dst == 0) ? g_H : (dst == 1 ? g_Z1 : g_Z2);

    const int bm = blockIdx.y * BM;
    const int bn = blockIdx.x * BN;
    const int tid = threadIdx.x;
    const int tx = tid & 15, ty = tid >> 4;

    float acc[8][8];
#pragma unroll
    for (int i = 0; i < 8; i++)
#pragma unroll
        for (int j = 0; j < 8; j++) acc[i][j] = 0.f;

    for (int k0 = 0; k0 < DDIM; k0 += BK) {
#pragma unroll
        for (int it = 0; it < 2; it++) {
            int idx = tid + it * 256;
            int row = idx >> 2;
            int kc  = (idx & 3) << 2;
            float4 va = *reinterpret_cast<const float4*>(A + (size_t)(bm + row) * DDIM + k0 + kc);
            As[kc + 0][row] = va.x; As[kc + 1][row] = va.y;
            As[kc + 2][row] = va.z; As[kc + 3][row] = va.w;
            float4 vb = *reinterpret_cast<const float4*>(W + (size_t)(bn + row) * DDIM + k0 + kc);
            Bs[kc + 0][row] = vb.x; Bs[kc + 1][row] = vb.y;
            Bs[kc + 2][row] = vb.z; Bs[kc + 3][row] = vb.w;
        }
        __syncthreads();
#pragma unroll
        for (int k = 0; k < BK; k++) {
            float4 a0 = *reinterpret_cast<const float4*>(&As[k][ty * 8]);
            float4 a1 = *reinterpret_cast<const float4*>(&As[k][ty * 8 + 4]);
            float4 b0 = *reinterpret_cast<const float4*>(&Bs[k][tx * 8]);
            float4 b1 = *reinterpret_cast<const float4*>(&Bs[k][tx * 8 + 4]);
            float a[8] = {a0.x, a0.y, a0.z, a0.w, a1.x, a1.y, a1.z, a1.w};
            float b[8] = {b0.x, b0.y, b0.z, b0.w, b1.x, b1.y, b1.z, b1.w};
#pragma unroll
            for (int i = 0; i < 8; i++)
#pragma unroll
                for (int j = 0; j < 8; j++) acc[i][j] = fmaf(a[i], b[j], acc[i][j]);
        }
        __syncthreads();
    }

    float bv[8];
#pragma unroll
    for (int j = 0; j < 8; j++) bv[j] = bias[bn + tx * 8 + j];
#pragma unroll
    for (int i = 0; i < 8; i++) {
        float* crow = C + (size_t)(bm + ty * 8 + i) * DDIM + bn + tx * 8;
#pragma unroll
        for (int j = 0; j < 8; j++) {
            float v = acc[i][j] + bv[j];
            if (ACT) v = v > 0.f ? v : expm1f(v);
            crow[j] = v;
        }
    }
}

// ---------------- row normalization: f32 in place + bf16 copy ----------------
__global__ void normalize_kernel() {
    float* Z = (blockIdx.y == 0) ? g_Z1 : g_Z2;
    __nv_bfloat16* Zh = (blockIdx.y == 0) ? g_Z1h : g_Z2h;
    int row  = blockIdx.x * 8 + (threadIdx.x >> 5);
    int lane = threadIdx.x & 31;
    float4* p = reinterpret_cast<float4*>(Z + (size_t)row * DDIM);
    float4 v0 = p[lane];
    float4 v1 = p[lane + 32];
    float s = v0.x*v0.x + v0.y*v0.y + v0.z*v0.z + v0.w*v0.w
            + v1.x*v1.x + v1.y*v1.y + v1.z*v1.z + v1.w*v1.w;
#pragma unroll
    for (int off = 16; off >= 1; off >>= 1) s += __shfl_xor_sync(0xffffffffu, s, off);
    float inv = 1.f / fmaxf(sqrtf(s), 1e-12f);
    v0.x *= inv; v0.y *= inv; v0.z *= inv; v0.w *= inv;
    v1.x *= inv; v1.y *= inv; v1.z *= inv; v1.w *= inv;
    p[lane] = v0; p[lane + 32] = v1;

    __nv_bfloat162* ph = reinterpret_cast<__nv_bfloat162*>(Zh + (size_t)row * DDIM);
    ph[lane * 2 + 0] = __floats2bfloat162_rn(v0.x, v0.y);
    ph[lane * 2 + 1] = __floats2bfloat162_rn(v0.z, v0.w);
    ph[(lane + 32) * 2 + 0] = __floats2bfloat162_rn(v1.x, v1.y);
    ph[(lane + 32) * 2 + 1] = __floats2bfloat162_rn(v1.z, v1.w);
}

// ---------------- diagonal of exp(z1.z2/tau) (fp32) --------------------------
__global__ void diag_kernel() {
    int row  = blockIdx.x * 8 + (threadIdx.x >> 5);
    int lane = threadIdx.x & 31;
    const float4* p1 = reinterpret_cast<const float4*>(g_Z1 + (size_t)row * DDIM);
    const float4* p2 = reinterpret_cast<const float4*>(g_Z2 + (size_t)row * DDIM);
    float4 a0 = p1[lane], a1 = p1[lane + 32];
    float4 b0 = p2[lane], b1 = p2[lane + 32];
    float s = a0.x*b0.x + a0.y*b0.y + a0.z*b0.z + a0.w*b0.w
            + a1.x*b1.x + a1.y*b1.y + a1.z*b1.z + a1.w*b1.w;
#pragma unroll
    for (int off = 16; off >= 1; off >>= 1) s += __shfl_xor_sync(0xffffffffu, s, off);
    if (lane == 0) g_D12[row] = __expf(s * INV_TAU);
}

// ---------------- warp-MMA Gram: rowsum (and colsum) of exp(A.B^T / tau) -----
// selA/selB: 1->Z1h, 2->Z2h. rsel: 0->R11, 1->R22, 2->R12r. COL: also R12c.
template <bool COL>
__global__ __launch_bounds__(256, 2)
void gram_mma_kernel(int selA, int selB, int rsel) {
    extern __shared__ __align__(128) char smem[];
    const uint32_t sbase = smem_u32(smem);

    const int tid  = threadIdx.x;
    const int wid  = tid >> 5;
    const int lane = tid & 31;
    const int b    = blockIdx.z;

    const __nv_bfloat16* Ah = (selA == 1) ? g_Z1h : g_Z2h;
    const __nv_bfloat16* Bh = (selB == 1) ? g_Z1h : g_Z2h;
    float* rowsum = (rsel == 0) ? g_R11 : (rsel == 1) ? g_R22 : g_R12r;

    const int bm = blockIdx.y * GBM;
    const int bn = blockIdx.x * GBN;
    const __nv_bfloat16* Abase = Ah + ((size_t)b * LSEQ + bm) * DDIM;
    const __nv_bfloat16* Bbase = Bh + ((size_t)b * LSEQ + bn) * DDIM;

    // warp tile: 4 warps along M, 2 along N; each warp 32(M) x 64(N)
    const int wm = (wid & 3) * 32;
    const int wn = (wid >> 2) * 64;

    float acc[2][8][4];
#pragma unroll
    for (int mi = 0; mi < 2; mi++)
#pragma unroll
        for (int nj = 0; nj < 8; nj++)
#pragma unroll
            for (int c = 0; c < 4; c++) acc[mi][nj][c] = 0.f;

    // async load of one K-stage (64 halves per row) into buffer `buf`
    auto load_stage = [&](int buf, int kt) {
        const int kofs = kt * GBK;
#pragma unroll
        for (int it = 0; it < 4; it++) {
            int idx = tid + it * 256;            // 0..1023
            int row = idx >> 3;                  // 0..127
            int ch  = idx & 7;                   // 16B chunk
            cp_async16(sbase + buf * G_TILE_BYTES + row * (GPAD * 2) + ch * 16,
                       Abase + (size_t)row * DDIM + kofs + ch * 8);
            cp_async16(sbase + G_B_OFF + buf * G_TILE_BYTES + row * (GPAD * 2) + ch * 16,
                       Bbase + (size_t)row * DDIM + kofs + ch * 8);
        }
    };

    load_stage(0, 0);
    cp_commit();

    int buf = 0;
#pragma unroll
    for (int kt = 0; kt < DDIM / GBK; kt++) {
        if (kt + 1 < DDIM / GBK) {
            load_stage(buf ^ 1, kt + 1);
            cp_commit();
            cp_wait<1>();
        } else {
            cp_wait<0>();
        }
        __syncthreads();

        const uint32_t aBuf = sbase + buf * G_TILE_BYTES;
        const uint32_t bBuf = sbase + G_B_OFF + buf * G_TILE_BYTES;

#pragma unroll
        for (int ks = 0; ks < GBK / 16; ks++) {
            // A fragments: two 16x16 tiles (rows wm..wm+31)
            uint32_t afr[2][4];
#pragma unroll
            for (int mi = 0; mi < 2; mi++) {
                int r = wm + mi * 16 + (lane & 15);
                int c = ks * 16 + (lane >> 4) * 8;
                ldm_x4(afr[mi][0], afr[mi][1], afr[mi][2], afr[mi][3],
                       aBuf + r * (GPAD * 2) + c * 2);
            }
            // B fragments: 4 ldmatrix.x4, each covering 16 n-rows x 16 k
            uint32_t bfr[4][4];
#pragma unroll
            for (int bi = 0; bi < 4; bi++) {
                int r = wn + bi * 16 + (lane & 7) + ((lane >> 4) << 3);
                int c = ks * 16 + ((lane >> 3) & 1) * 8;
                ldm_x4(bfr[bi][0], bfr[bi][1], bfr[bi][2], bfr[bi][3],
                       bBuf + r * (GPAD * 2) + c * 2);
            }
#pragma unroll
            for (int mi = 0; mi < 2; mi++)
#pragma unroll
                for (int bi = 0; bi < 4; bi++) {
                    mma_bf16(acc[mi][bi * 2 + 0], afr[mi], &bfr[bi][0]);
                    mma_bf16(acc[mi][bi * 2 + 1], afr[mi], &bfr[bi][2]);
                }
        }
        __syncthreads();
        buf ^= 1;
    }

    // ---- epilogue: exp + row sums (+ col sums)
    float rs[2][2] = {{0.f, 0.f}, {0.f, 0.f}};
    float cs[8][2];
    if (COL) {
#pragma unroll
        for (int nj = 0; nj < 8; nj++) { cs[nj][0] = 0.f; cs[nj][1] = 0.f; }
    }
#pragma unroll
    for (int mi = 0; mi < 2; mi++)
#pragma unroll
        for (int nj = 0; nj < 8; nj++) {
            float e0 = __expf(acc[mi][nj][0] * INV_TAU);
            float e1 = __expf(acc[mi][nj][1] * INV_TAU);
            float e2 = __expf(acc[mi][nj][2] * INV_TAU);
            float e3 = __expf(acc[mi][nj][3] * INV_TAU);
            rs[mi][0] += e0 + e1;
            rs[mi][1] += e2 + e3;
            if (COL) { cs[nj][0] += e0 + e2; cs[nj][1] += e1 + e3; }
        }

    // row reduce across the 4 lanes sharing a row (lane bits 0-1)
#pragma unroll
    for (int off = 1; off <= 2; off <<= 1)
#pragma unroll
        for (int mi = 0; mi < 2; mi++) {
            rs[mi][0] += __shfl_xor_sync(0xffffffffu, rs[mi][0], off);
            rs[mi][1] += __shfl_xor_sync(0xffffffffu, rs[mi][1], off);
        }
    if ((lane & 3) == 0) {
#pragma unroll
        for (int mi = 0; mi < 2; mi++) {
            int row = bm + wm + mi * 16 + (lane >> 2);
            atomicAdd(&rowsum[(size_t)b * LSEQ + row], rs[mi][0]);
            atomicAdd(&rowsum[(size_t)b * LSEQ + row + 8], rs[mi][1]);
        }
    }

    if (COL) {
        // col reduce across the 8 lane-groups sharing a column (lane bits 2-4)
#pragma unroll
        for (int off = 4; off <= 16; off <<= 1)
#pragma unroll
            for (int nj = 0; nj < 8; nj++) {
                cs[nj][0] += __shfl_xor_sync(0xffffffffu, cs[nj][0], off);
                cs[nj][1] += __shfl_xor_sync(0xffffffffu, cs[nj][1], off);
            }
        if (lane < 4) {
#pragma unroll
            for (int nj = 0; nj < 8; nj++) {
                int col = bn + wn + nj * 8 + lane * 2;
                atomicAdd(&g_R12c[(size_t)b * LSEQ + col], cs[nj][0]);
                atomicAdd(&g_R12c[(size_t)b * LSEQ + col + 1], cs[nj][1]);
            }
        }
    }
}

// ---------------- final scalar reduction -------------------------------------
__global__ void final_kernel(float* __restrict__ out) {
    __shared__ double sred[256];
    const float E2 = 7.3890560989306495f;   // exp(||z||^2 / tau) = exp(2)
    double acc = 0.0;
    for (int n = threadIdx.x; n < NTOK; n += 256) {
        float d1 = g_R11[n] + g_R12r[n] - E2;
        float d2 = g_R22[n] + g_R12c[n] - E2;
        acc += (double)(logf(d1) + logf(d2) - 2.f * logf(g_D12[n]));
    }
    sred[threadIdx.x] = acc;
    __syncthreads();
    for (int s = 128; s > 0; s >>= 1) {
        if (threadIdx.x < s) sred[threadIdx.x] += sred[threadIdx.x + s];
        __syncthreads();
    }
    if (threadIdx.x == 0) out[0] = (float)(sred[0] / (2.0 * BATCH));
}

// ---------------- launch -------------------------------------------------------
extern "C" void kernel_launch(void* const* d_in, const int* in_sizes, int n_in,
                              void* d_out, int out_size) {
    (void)in_sizes; (void)n_in; (void)out_size;
    const float* X1 = (const float*)d_in[0];
    const float* X2 = (const float*)d_in[1];
    const float* W1 = (const float*)d_in[2];
    const float* b1 = (const float*)d_in[3];
    const float* W2 = (const float*)d_in[4];
    const float* b2 = (const float*)d_in[5];
    float* out = (float*)d_out;

    cudaFuncSetAttribute(gram_mma_kernel<false>,
                         cudaFuncAttributeMaxDynamicSharedMemorySize, G_SMEM_TOTAL);
    cudaFuncSetAttribute(gram_mma_kernel<true>,
                         cudaFuncAttributeMaxDynamicSharedMemorySize, G_SMEM_TOTAL);

    zero_kernel<<<(NTOK + 255) / 256, 256>>>();

    dim3 gproj(DDIM / BN, NTOK / BM);     // (2, 128)
    gemm_nt_bias<1><<<gproj, 256>>>(X1, W1, b1, 0, 0);
    gemm_nt_bias<0><<<gproj, 256>>>(nullptr, W2, b2, 1, 1);
    gemm_nt_bias<1><<<gproj, 256>>>(X2, W1, b1, 0, 0);
    gemm_nt_bias<0><<<gproj, 256>>>(nullptr, W2, b2, 1, 2);

    normalize_kernel<<<dim3(NTOK / 8, 2), 256>>>();
    diag_kernel<<<NTOK / 8, 256>>>();

    dim3 ggram(LSEQ / GBN, LSEQ / GBM, BATCH);   // (32, 32, 4)
    gram_mma_kernel<false><<<ggram, 256, G_SMEM_TOTAL>>>(1, 1, 0);   // R11
    gram_mma_kernel<false><<<ggram, 256, G_SMEM_TOTAL>>>(2, 2, 1);   // R22
    gram_mma_kernel<true ><<<ggram, 256, G_SMEM_TOTAL>>>(1, 2, 2);   // R12 row+col

    final_kernel<<<1, 256>>>(out);
}

// round 4
// speedup vs baseline: 7.7318x; 1.9626x over previous
#include <cuda_runtime.h>
#include <cuda_bf16.h>
#include <math.h>
#include <stdint.h>

// Problem constants
#define BATCH 4
#define LSEQ 4096
#define DDIM 256
#define NTOK (BATCH * LSEQ)   // 16384
#define INV_TAU 2.0f

// MMA tiling: CTA 128x128, K staged 64 at a time, double buffered
#define GBM 128
#define GBN 128
#define GBK 64
#define GPAD 72                            // halves per SMEM row (64 + 8 pad)
#define G_TILE_BYTES (GBM * GPAD * 2)      // 18432 per buffer
#define G_B_OFF (2 * G_TILE_BYTES)
#define G_SMEM_TOTAL (4 * G_TILE_BYTES)    // 73728

// ---------------- scratch (device globals; no allocation allowed) -----------
__device__ __nv_bfloat16 g_X1h[NTOK * DDIM];
__device__ __nv_bfloat16 g_X2h[NTOK * DDIM];
__device__ __nv_bfloat16 g_W1h[DDIM * DDIM];
__device__ __nv_bfloat16 g_W2h[DDIM * DDIM];
__device__ __nv_bfloat16 g_Hh [NTOK * DDIM];
__device__ float g_Z1[NTOK * DDIM];
__device__ float g_Z2[NTOK * DDIM];
__device__ __nv_bfloat16 g_Z1h[NTOK * DDIM];
__device__ __nv_bfloat16 g_Z2h[NTOK * DDIM];
__device__ float g_R11 [NTOK];
__device__ float g_R22 [NTOK];
__device__ float g_R12r[NTOK];
__device__ float g_R12c[NTOK];
__device__ float g_D12 [NTOK];

// ---------------- PTX helpers ------------------------------------------------
__device__ __forceinline__ uint32_t smem_u32(const void* p) {
    uint32_t a;
    asm("{ .reg .u64 t; cvta.to.shared.u64 t, %1; cvt.u32.u64 %0, t; }"
        : "=r"(a) : "l"(p));
    return a;
}

__device__ __forceinline__ void cp_async16(uint32_t s, const void* g) {
    asm volatile("cp.async.cg.shared.global [%0], [%1], 16;" :: "r"(s), "l"(g));
}
__device__ __forceinline__ void cp_commit() {
    asm volatile("cp.async.commit_group;");
}
template <int N>
__device__ __forceinline__ void cp_wait() {
    asm volatile("cp.async.wait_group %0;" :: "n"(N));
}

__device__ __forceinline__ void ldm_x4(uint32_t& r0, uint32_t& r1, uint32_t& r2,
                                       uint32_t& r3, uint32_t addr) {
    asm volatile("ldmatrix.sync.aligned.m8n8.x4.shared.b16 {%0,%1,%2,%3}, [%4];"
                 : "=r"(r0), "=r"(r1), "=r"(r2), "=r"(r3) : "r"(addr));
}

__device__ __forceinline__ void mma_bf16(float* d, const uint32_t* a,
                                         const uint32_t* b) {
    asm volatile(
        "mma.sync.aligned.m16n8k16.row.col.f32.bf16.bf16.f32 "
        "{%0,%1,%2,%3}, {%4,%5,%6,%7}, {%8,%9}, {%0,%1,%2,%3};"
        : "+f"(d[0]), "+f"(d[1]), "+f"(d[2]), "+f"(d[3])
        : "r"(a[0]), "r"(a[1]), "r"(a[2]), "r"(a[3]), "r"(b[0]), "r"(b[1]));
}

// ---------------- init / convert ---------------------------------------------
__global__ void zero_kernel() {
    int i = blockIdx.x * blockDim.x + threadIdx.x;
    if (i < NTOK) {
        g_R11[i] = 0.f; g_R22[i] = 0.f; g_R12r[i] = 0.f; g_R12c[i] = 0.f;
    }
}

__global__ void cvt_kernel(const float* __restrict__ src, int dstsel, int n4) {
    __nv_bfloat16* dst = (dstsel == 0) ? g_X1h : (dstsel == 1) ? g_X2h
                       : (dstsel == 2) ? g_W1h : g_W2h;
    int i = blockIdx.x * blockDim.x + threadIdx.x;
    if (i < n4) {
        float4 v = reinterpret_cast<const float4*>(src)[i];
        __nv_bfloat162* d = reinterpret_cast<__nv_bfloat162*>(dst) + i * 2;
        d[0] = __floats2bfloat162_rn(v.x, v.y);
        d[1] = __floats2bfloat162_rn(v.z, v.w);
    }
}

// ---------------- shared MMA mainloop pieces ---------------------------------
// warp tile: 4 warps along M, 2 along N; each warp 32(M) x 64(N), acc[2][8][4].

// ---------------- projection GEMM (bf16 MMA): C = act(A @ W^T + bias) --------
// ACT=1: ELU, output bf16 -> g_Hh. ACT=0: identity, output f32 -> g_Z1/g_Z2.
template <int ACT>
__global__ __launch_bounds__(256, 2)
void proj_mma(int srcsel, int wsel, const float* __restrict__ bias, int dstsel) {
    extern __shared__ __align__(128) char smem[];
    const uint32_t sbase = smem_u32(smem);

    const int tid  = threadIdx.x;
    const int wid  = tid >> 5;
    const int lane = tid & 31;

    const __nv_bfloat16* A = (srcsel == 0) ? g_X1h : (srcsel == 1) ? g_X2h : g_Hh;
    const __nv_bfloat16* W = (wsel == 1) ? g_W1h : g_W2h;
    float* Cf = (dstsel == 1) ? g_Z1 : g_Z2;

    const int bm = blockIdx.y * GBM;
    const int bn = blockIdx.x * GBN;
    const __nv_bfloat16* Abase = A + (size_t)bm * DDIM;
    const __nv_bfloat16* Bbase = W + (size_t)bn * DDIM;

    const int wm = (wid & 3) * 32;
    const int wn = (wid >> 2) * 64;

    float acc[2][8][4];
#pragma unroll
    for (int mi = 0; mi < 2; mi++)
#pragma unroll
        for (int nj = 0; nj < 8; nj++)
#pragma unroll
            for (int c = 0; c < 4; c++) acc[mi][nj][c] = 0.f;

    auto load_stage = [&](int buf, int kt) {
        const int kofs = kt * GBK;
#pragma unroll
        for (int it = 0; it < 4; it++) {
            int idx = tid + it * 256;
            int row = idx >> 3;
            int ch  = idx & 7;
            cp_async16(sbase + buf * G_TILE_BYTES + row * (GPAD * 2) + ch * 16,
                       Abase + (size_t)row * DDIM + kofs + ch * 8);
            cp_async16(sbase + G_B_OFF + buf * G_TILE_BYTES + row * (GPAD * 2) + ch * 16,
                       Bbase + (size_t)row * DDIM + kofs + ch * 8);
        }
    };

    load_stage(0, 0);
    cp_commit();

    int buf = 0;
#pragma unroll
    for (int kt = 0; kt < DDIM / GBK; kt++) {
        if (kt + 1 < DDIM / GBK) {
            load_stage(buf ^ 1, kt + 1);
            cp_commit();
            cp_wait<1>();
        } else {
            cp_wait<0>();
        }
        __syncthreads();

        const uint32_t aBuf = sbase + buf * G_TILE_BYTES;
        const uint32_t bBuf = sbase + G_B_OFF + buf * G_TILE_BYTES;

#pragma unroll
        for (int ks = 0; ks < GBK / 16; ks++) {
            uint32_t afr[2][4];
#pragma unroll
            for (int mi = 0; mi < 2; mi++) {
                int r = wm + mi * 16 + (lane & 15);
                int c = ks * 16 + (lane >> 4) * 8;
                ldm_x4(afr[mi][0], afr[mi][1], afr[mi][2], afr[mi][3],
                       aBuf + r * (GPAD * 2) + c * 2);
            }
            uint32_t bfr[4][4];
#pragma unroll
            for (int bi = 0; bi < 4; bi++) {
                int r = wn + bi * 16 + (lane & 7) + ((lane >> 4) << 3);
                int c = ks * 16 + ((lane >> 3) & 1) * 8;
                ldm_x4(bfr[bi][0], bfr[bi][1], bfr[bi][2], bfr[bi][3],
                       bBuf + r * (GPAD * 2) + c * 2);
            }
#pragma unroll
            for (int mi = 0; mi < 2; mi++)
#pragma unroll
                for (int bi = 0; bi < 4; bi++) {
                    mma_bf16(acc[mi][bi * 2 + 0], afr[mi], &bfr[bi][0]);
                    mma_bf16(acc[mi][bi * 2 + 1], afr[mi], &bfr[bi][2]);
                }
        }
        __syncthreads();
        buf ^= 1;
    }

    // epilogue: bias + activation + store
#pragma unroll
    for (int mi = 0; mi < 2; mi++)
#pragma unroll
        for (int nj = 0; nj < 8; nj++) {
            int col = bn + wn + nj * 8 + (lane & 3) * 2;
            float b0 = __ldg(&bias[col]);
            float b1 = __ldg(&bias[col + 1]);
            int r0 = bm + wm + mi * 16 + (lane >> 2);
            float v00 = acc[mi][nj][0] + b0, v01 = acc[mi][nj][1] + b1;
            float v10 = acc[mi][nj][2] + b0, v11 = acc[mi][nj][3] + b1;
            if (ACT) {
                v00 = v00 > 0.f ? v00 : expm1f(v00);
                v01 = v01 > 0.f ? v01 : expm1f(v01);
                v10 = v10 > 0.f ? v10 : expm1f(v10);
                v11 = v11 > 0.f ? v11 : expm1f(v11);
                *reinterpret_cast<__nv_bfloat162*>(g_Hh + (size_t)r0 * DDIM + col)
                    = __floats2bfloat162_rn(v00, v01);
                *reinterpret_cast<__nv_bfloat162*>(g_Hh + (size_t)(r0 + 8) * DDIM + col)
                    = __floats2bfloat162_rn(v10, v11);
            } else {
                *reinterpret_cast<float2*>(Cf + (size_t)r0 * DDIM + col)
                    = make_float2(v00, v01);
                *reinterpret_cast<float2*>(Cf + (size_t)(r0 + 8) * DDIM + col)
                    = make_float2(v10, v11);
            }
        }
}

// ---------------- row normalization: f32 in place + bf16 copy ----------------
__global__ void normalize_kernel() {
    float* Z = (blockIdx.y == 0) ? g_Z1 : g_Z2;
    __nv_bfloat16* Zh = (blockIdx.y == 0) ? g_Z1h : g_Z2h;
    int row  = blockIdx.x * 8 + (threadIdx.x >> 5);
    int lane = threadIdx.x & 31;
    float4* p = reinterpret_cast<float4*>(Z + (size_t)row * DDIM);
    float4 v0 = p[lane];
    float4 v1 = p[lane + 32];
    float s = v0.x*v0.x + v0.y*v0.y + v0.z*v0.z + v0.w*v0.w
            + v1.x*v1.x + v1.y*v1.y + v1.z*v1.z + v1.w*v1.w;
#pragma unroll
    for (int off = 16; off >= 1; off >>= 1) s += __shfl_xor_sync(0xffffffffu, s, off);
    float inv = 1.f / fmaxf(sqrtf(s), 1e-12f);
    v0.x *= inv; v0.y *= inv; v0.z *= inv; v0.w *= inv;
    v1.x *= inv; v1.y *= inv; v1.z *= inv; v1.w *= inv;
    p[lane] = v0; p[lane + 32] = v1;

    __nv_bfloat162* ph = reinterpret_cast<__nv_bfloat162*>(Zh + (size_t)row * DDIM);
    ph[lane * 2 + 0] = __floats2bfloat162_rn(v0.x, v0.y);
    ph[lane * 2 + 1] = __floats2bfloat162_rn(v0.z, v0.w);
    ph[(lane + 32) * 2 + 0] = __floats2bfloat162_rn(v1.x, v1.y);
    ph[(lane + 32) * 2 + 1] = __floats2bfloat162_rn(v1.z, v1.w);
}

// ---------------- diagonal of exp(z1.z2/tau) (fp32) --------------------------
__global__ void diag_kernel() {
    int row  = blockIdx.x * 8 + (threadIdx.x >> 5);
    int lane = threadIdx.x & 31;
    const float4* p1 = reinterpret_cast<const float4*>(g_Z1 + (size_t)row * DDIM);
    const float4* p2 = reinterpret_cast<const float4*>(g_Z2 + (size_t)row * DDIM);
    float4 a0 = p1[lane], a1 = p1[lane + 32];
    float4 b0 = p2[lane], b1 = p2[lane + 32];
    float s = a0.x*b0.x + a0.y*b0.y + a0.z*b0.z + a0.w*b0.w
            + a1.x*b1.x + a1.y*b1.y + a1.z*b1.z + a1.w*b1.w;
#pragma unroll
    for (int off = 16; off >= 1; off >>= 1) s += __shfl_xor_sync(0xffffffffu, s, off);
    if (lane == 0) g_D12[row] = __expf(s * INV_TAU);
}

// ---------------- warp-MMA Gram ------------------------------------------------
// SYM=1: A=B=Z(sel); triangular tiles j>=i; rowsum->R, colsum->R (off-diag only).
// SYM=0: A=Z1, B=Z2; full grid; rowsum->R12r, colsum->R12c.
template <int SYM>
__global__ __launch_bounds__(256, 2)
void gram_mma(int sel) {
    const int iy = blockIdx.y, jx = blockIdx.x;
    if (SYM && jx < iy) return;
    const bool do_col = SYM ? (jx != iy) : true;

    extern __shared__ __align__(128) char smem[];
    const uint32_t sbase = smem_u32(smem);

    const int tid  = threadIdx.x;
    const int wid  = tid >> 5;
    const int lane = tid & 31;
    const int b    = blockIdx.z;

    const __nv_bfloat16* Ah;
    const __nv_bfloat16* Bh;
    float* rowsum;
    float* colsum;
    if (SYM) {
        const __nv_bfloat16* Zh = (sel == 1) ? g_Z1h : g_Z2h;
        Ah = Zh; Bh = Zh;
        rowsum = (sel == 1) ? g_R11 : g_R22;
        colsum = rowsum;
    } else {
        Ah = g_Z1h; Bh = g_Z2h;
        rowsum = g_R12r; colsum = g_R12c;
    }

    const int bm = iy * GBM;
    const int bn = jx * GBN;
    const __nv_bfloat16* Abase = Ah + ((size_t)b * LSEQ + bm) * DDIM;
    const __nv_bfloat16* Bbase = Bh + ((size_t)b * LSEQ + bn) * DDIM;

    const int wm = (wid & 3) * 32;
    const int wn = (wid >> 2) * 64;

    float acc[2][8][4];
#pragma unroll
    for (int mi = 0; mi < 2; mi++)
#pragma unroll
        for (int nj = 0; nj < 8; nj++)
#pragma unroll
            for (int c = 0; c < 4; c++) acc[mi][nj][c] = 0.f;

    auto load_stage = [&](int buf, int kt) {
        const int kofs = kt * GBK;
#pragma unroll
        for (int it = 0; it < 4; it++) {
            int idx = tid + it * 256;
            int row = idx >> 3;
            int ch  = idx & 7;
            cp_async16(sbase + buf * G_TILE_BYTES + row * (GPAD * 2) + ch * 16,
                       Abase + (size_t)row * DDIM + kofs + ch * 8);
            cp_async16(sbase + G_B_OFF + buf * G_TILE_BYTES + row * (GPAD * 2) + ch * 16,
                       Bbase + (size_t)row * DDIM + kofs + ch * 8);
        }
    };

    load_stage(0, 0);
    cp_commit();

    int buf = 0;
#pragma unroll
    for (int kt = 0; kt < DDIM / GBK; kt++) {
        if (kt + 1 < DDIM / GBK) {
            load_stage(buf ^ 1, kt + 1);
            cp_commit();
            cp_wait<1>();
        } else {
            cp_wait<0>();
        }
        __syncthreads();

        const uint32_t aBuf = sbase + buf * G_TILE_BYTES;
        const uint32_t bBuf = sbase + G_B_OFF + buf * G_TILE_BYTES;

#pragma unroll
        for (int ks = 0; ks < GBK / 16; ks++) {
            uint32_t afr[2][4];
#pragma unroll
            for (int mi = 0; mi < 2; mi++) {
                int r = wm + mi * 16 + (lane & 15);
                int c = ks * 16 + (lane >> 4) * 8;
                ldm_x4(afr[mi][0], afr[mi][1], afr[mi][2], afr[mi][3],
                       aBuf + r * (GPAD * 2) + c * 2);
            }
            uint32_t bfr[4][4];
#pragma unroll
            for (int bi = 0; bi < 4; bi++) {
                int r = wn + bi * 16 + (lane & 7) + ((lane >> 4) << 3);
                int c = ks * 16 + ((lane >> 3) & 1) * 8;
                ldm_x4(bfr[bi][0], bfr[bi][1], bfr[bi][2], bfr[bi][3],
                       bBuf + r * (GPAD * 2) + c * 2);
            }
#pragma unroll
            for (int mi = 0; mi < 2; mi++)
#pragma unroll
                for (int bi = 0; bi < 4; bi++) {
                    mma_bf16(acc[mi][bi * 2 + 0], afr[mi], &bfr[bi][0]);
                    mma_bf16(acc[mi][bi * 2 + 1], afr[mi], &bfr[bi][2]);
                }
        }
        __syncthreads();
        buf ^= 1;
    }

    // ---- epilogue: exp + row sums (+ col sums)
    float rs[2][2] = {{0.f, 0.f}, {0.f, 0.f}};
    float cs[8][2];
#pragma unroll
    for (int nj = 0; nj < 8; nj++) { cs[nj][0] = 0.f; cs[nj][1] = 0.f; }

#pragma unroll
    for (int mi = 0; mi < 2; mi++)
#pragma unroll
        for (int nj = 0; nj < 8; nj++) {
            float e0 = __expf(acc[mi][nj][0] * INV_TAU);
            float e1 = __expf(acc[mi][nj][1] * INV_TAU);
            float e2 = __expf(acc[mi][nj][2] * INV_TAU);
            float e3 = __expf(acc[mi][nj][3] * INV_TAU);
            rs[mi][0] += e0 + e1;
            rs[mi][1] += e2 + e3;
            cs[nj][0] += e0 + e2;
            cs[nj][1] += e1 + e3;
        }

#pragma unroll
    for (int off = 1; off <= 2; off <<= 1)
#pragma unroll
        for (int mi = 0; mi < 2; mi++) {
            rs[mi][0] += __shfl_xor_sync(0xffffffffu, rs[mi][0], off);
            rs[mi][1] += __shfl_xor_sync(0xffffffffu, rs[mi][1], off);
        }
    if ((lane & 3) == 0) {
#pragma unroll
        for (int mi = 0; mi < 2; mi++) {
            int row = bm + wm + mi * 16 + (lane >> 2);
            atomicAdd(&rowsum[(size_t)b * LSEQ + row], rs[mi][0]);
            atomicAdd(&rowsum[(size_t)b * LSEQ + row + 8], rs[mi][1]);
        }
    }

    if (do_col) {
#pragma unroll
        for (int off = 4; off <= 16; off <<= 1)
#pragma unroll
            for (int nj = 0; nj < 8; nj++) {
                cs[nj][0] += __shfl_xor_sync(0xffffffffu, cs[nj][0], off);
                cs[nj][1] += __shfl_xor_sync(0xffffffffu, cs[nj][1], off);
            }
        if (lane < 4) {
#pragma unroll
            for (int nj = 0; nj < 8; nj++) {
                int col = bn + wn + nj * 8 + lane * 2;
                atomicAdd(&colsum[(size_t)b * LSEQ + col], cs[nj][0]);
                atomicAdd(&colsum[(size_t)b * LSEQ + col + 1], cs[nj][1]);
            }
        }
    }
}

// ---------------- final scalar reduction -------------------------------------
__global__ void final_kernel(float* __restrict__ out) {
    __shared__ double sred[256];
    const float E2 = 7.3890560989306495f;   // exp(||z||^2 / tau) = exp(2)
    double acc = 0.0;
    for (int n = threadIdx.x; n < NTOK; n += 256) {
        float d1 = g_R11[n] + g_R12r[n] - E2;
        float d2 = g_R22[n] + g_R12c[n] - E2;
        acc += (double)(logf(d1) + logf(d2) - 2.f * logf(g_D12[n]));
    }
    sred[threadIdx.x] = acc;
    __syncthreads();
    for (int s = 128; s > 0; s >>= 1) {
        if (threadIdx.x < s) sred[threadIdx.x] += sred[threadIdx.x + s];
        __syncthreads();
    }
    if (threadIdx.x == 0) out[0] = (float)(sred[0] / (2.0 * BATCH));
}

// ---------------- launch -------------------------------------------------------
extern "C" void kernel_launch(void* const* d_in, const int* in_sizes, int n_in,
                              void* d_out, int out_size) {
    (void)in_sizes; (void)n_in; (void)out_size;
    const float* X1 = (const float*)d_in[0];
    const float* X2 = (const float*)d_in[1];
    const float* W1 = (const float*)d_in[2];
    const float* b1 = (const float*)d_in[3];
    const float* W2 = (const float*)d_in[4];
    const float* b2 = (const float*)d_in[5];
    float* out = (float*)d_out;

    cudaFuncSetAttribute(proj_mma<0>, cudaFuncAttributeMaxDynamicSharedMemorySize, G_SMEM_TOTAL);
    cudaFuncSetAttribute(proj_mma<1>, cudaFuncAttributeMaxDynamicSharedMemorySize, G_SMEM_TOTAL);
    cudaFuncSetAttribute(gram_mma<0>, cudaFuncAttributeMaxDynamicSharedMemorySize, G_SMEM_TOTAL);
    cudaFuncSetAttribute(gram_mma<1>, cudaFuncAttributeMaxDynamicSharedMemorySize, G_SMEM_TOTAL);

    zero_kernel<<<(NTOK + 255) / 256, 256>>>();

    // bf16 conversions
    const int NX4 = NTOK * DDIM / 4;   // 1048576
    const int NW4 = DDIM * DDIM / 4;   // 16384
    cvt_kernel<<<NX4 / 256, 256>>>(X1, 0, NX4);
    cvt_kernel<<<NX4 / 256, 256>>>(X2, 1, NX4);
    cvt_kernel<<<NW4 / 256, 256>>>(W1, 2, NW4);
    cvt_kernel<<<NW4 / 256, 256>>>(W2, 3, NW4);

    // projections (bf16 MMA): grid (N-tiles=2, M-tiles=128)
    dim3 gproj(DDIM / GBN, NTOK / GBM);
    proj_mma<1><<<gproj, 256, G_SMEM_TOTAL>>>(0, 1, b1, 0);   // H = ELU(X1 W1^T + b1)
    proj_mma<0><<<gproj, 256, G_SMEM_TOTAL>>>(2, 2, b2, 1);   // Z1 = H W2^T + b2
    proj_mma<1><<<gproj, 256, G_SMEM_TOTAL>>>(1, 1, b1, 0);   // H = ELU(X2 W1^T + b1)
    proj_mma<0><<<gproj, 256, G_SMEM_TOTAL>>>(2, 2, b2, 2);   // Z2 = H W2^T + b2

    normalize_kernel<<<dim3(NTOK / 8, 2), 256>>>();
    diag_kernel<<<NTOK / 8, 256>>>();

    dim3 ggram(LSEQ / GBN, LSEQ / GBM, BATCH);   // (32, 32, 4)
    gram_mma<1><<<ggram, 256, G_SMEM_TOTAL>>>(1);   // R11 (triangular)
    gram_mma<1><<<ggram, 256, G_SMEM_TOTAL>>>(2);   // R22 (triangular)
    gram_mma<0><<<ggram, 256, G_SMEM_TOTAL>>>(0);   // R12 row + col

    final_kernel<<<1, 256>>>(out);
}